// round 14
// baseline (speedup 1.0000x reference)
#include <cuda_runtime.h>
#include <math.h>

#define TT 2048
#define DD 1024
#define KQ 32
#define NT 8192
#define KTOP 4

typedef unsigned long long ull;

// scratch
__device__ float g_P[4][NT * 64];           // proj partials (k-split 4)
__device__ float2 g_Qhl[NT * 32];           // [row][k] (hi,lo)
__device__ float2 g_Khl[NT * 32];           // [row][k] (hi,lo)
__device__ float g_cv[NT * 8];              // candidate values [row][half][4]
__device__ __align__(16) int g_ci[NT * 8];  // candidate indices

// ---- packed f32x2 helpers (proj) -------------------------------------------
__device__ __forceinline__ void unpack2(ull v, float& lo, float& hi) {
    asm("mov.b64 {%0, %1}, %2;" : "=f"(lo), "=f"(hi) : "l"(v));
}
__device__ __forceinline__ ull ffma2(ull a, ull b, ull c) {
    ull d;
    asm("fma.rn.f32x2 %0, %1, %2, %3;" : "=l"(d) : "l"(a), "l"(b), "l"(c));
    return d;
}

// ---- tf32 helpers -----------------------------------------------------------
__device__ __forceinline__ float2 tf_split(float x) {
    unsigned u; asm("cvt.rna.tf32.f32 %0, %1;" : "=r"(u) : "f"(x));
    float h = __uint_as_float(u);
    return make_float2(h, x - h);
}
__device__ __forceinline__ void mma8(float* c, unsigned a0, unsigned a1,
                                     unsigned a2, unsigned a3,
                                     unsigned b0, unsigned b1) {
    asm volatile(
        "mma.sync.aligned.m16n8k8.row.col.f32.tf32.tf32.f32 "
        "{%0,%1,%2,%3}, {%4,%5,%6,%7}, {%8,%9}, {%0,%1,%2,%3};"
        : "+f"(c[0]), "+f"(c[1]), "+f"(c[2]), "+f"(c[3])
        : "r"(a0), "r"(a1), "r"(a2), "r"(a3), "r"(b0), "r"(b1));
}
__device__ __forceinline__ void upd4(float* v, int* ix, float s, int si) {
    if (s > v[3]) {
        if (s > v[1]) {
            v[3] = v[2]; ix[3] = ix[2]; v[2] = v[1]; ix[2] = ix[1];
            if (s > v[0]) { v[1] = v[0]; ix[1] = ix[0]; v[0] = s; ix[0] = si; }
            else          { v[1] = s; ix[1] = si; }
        } else {
            if (s > v[2]) { v[3] = v[2]; ix[3] = ix[2]; v[2] = s; ix[2] = si; }
            else          { v[3] = s; ix[3] = si; }
        }
    }
}

// ---------------------------------------------------------------------------
// Kernel 1 (R5-proven): projection partials. grid = 512, 256 thr.
// ---------------------------------------------------------------------------
__global__ __launch_bounds__(256) void proj_kernel(
    const float* __restrict__ x, const float* __restrict__ Wq,
    const float* __restrict__ Wk)
{
    __shared__ __align__(16) float Xd[32][132];
    __shared__ __align__(16) float Wt[32][68];

    const int tid  = threadIdx.x;
    const int row0 = (blockIdx.x >> 2) * 64;
    const int kh   = blockIdx.x & 3;
    const int rg   = tid >> 4;
    const int tc   = tid & 15;
    const int r0   = rg * 4;

    ull acc[4][2];
    #pragma unroll
    for (int i = 0; i < 4; i++) { acc[i][0] = 0ULL; acc[i][1] = 0ULL; }

    for (int kt = 0; kt < 8; kt++) {
        const int kb = kh * 256 + kt * 32;
        #pragma unroll
        for (int l = 0; l < 2; l++) {
            int f = tid + l * 256;
            int row = f >> 3, kc = f & 7;
            float4 v = *(const float4*)&x[(size_t)(row0 + row) * DD + kb + kc * 4];
            *(float2*)&Xd[kc * 4 + 0][2 * row] = make_float2(v.x, v.x);
            *(float2*)&Xd[kc * 4 + 1][2 * row] = make_float2(v.y, v.y);
            *(float2*)&Xd[kc * 4 + 2][2 * row] = make_float2(v.z, v.z);
            *(float2*)&Xd[kc * 4 + 3][2 * row] = make_float2(v.w, v.w);
        }
        #pragma unroll
        for (int l = 0; l < 2; l++) {
            int f = tid + l * 256;
            int col = f >> 3, kc = f & 7;
            const float* Wr = (col < KQ) ? &Wq[col * DD] : &Wk[(col - KQ) * DD];
            float4 w = *(const float4*)&Wr[kb + kc * 4];
            Wt[kc * 4 + 0][col] = w.x;
            Wt[kc * 4 + 1][col] = w.y;
            Wt[kc * 4 + 2][col] = w.z;
            Wt[kc * 4 + 3][col] = w.w;
        }
        __syncthreads();

        #pragma unroll
        for (int k = 0; k < 32; k++) {
            ulonglong2 xa = *(const ulonglong2*)&Xd[k][2 * r0];
            ulonglong2 xb = *(const ulonglong2*)&Xd[k][2 * r0 + 4];
            ull w0 = *(const ull*)&Wt[k][2 * tc];
            ull w1 = *(const ull*)&Wt[k][2 * tc + 32];
            ull xr[4] = { xa.x, xa.y, xb.x, xb.y };
            #pragma unroll
            for (int i = 0; i < 4; i++) {
                acc[i][0] = ffma2(xr[i], w0, acc[i][0]);
                acc[i][1] = ffma2(xr[i], w1, acc[i][1]);
            }
        }
        __syncthreads();
    }

    #pragma unroll
    for (int i = 0; i < 4; i++) {
        size_t r = (size_t)(row0 + r0 + i) * 64;
        float lo, hi;
        unpack2(acc[i][0], lo, hi);
        *(float2*)&g_P[kh][r + 2 * tc] = make_float2(lo, hi);
        unpack2(acc[i][1], lo, hi);
        *(float2*)&g_P[kh][r + 2 * tc + 32] = make_float2(lo, hi);
    }
}

// ---------------------------------------------------------------------------
// Kernel 2: reduce partials + bias; emit Q/K [row][k] packed (hi,lo).
// ---------------------------------------------------------------------------
__global__ __launch_bounds__(256) void reduce_split(
    const float* __restrict__ bq, const float* __restrict__ bk)
{
    const int tid  = threadIdx.x;
    const int row0 = blockIdx.x * 64;

    #pragma unroll
    for (int l = 0; l < 4; l++) {
        int f = tid + l * 256;
        int row = f >> 4, c4 = f & 15;
        size_t base = (size_t)(row0 + row) * 64 + c4 * 4;
        float4 a = *(const float4*)&g_P[0][base];
        float4 p1 = *(const float4*)&g_P[1][base];
        float4 p2 = *(const float4*)&g_P[2][base];
        float4 p3 = *(const float4*)&g_P[3][base];
        float4 s;
        s.x = ((a.x + p1.x) + p2.x) + p3.x;
        s.y = ((a.y + p1.y) + p2.y) + p3.y;
        s.z = ((a.z + p1.z) + p2.z) + p3.z;
        s.w = ((a.w + p1.w) + p2.w) + p3.w;
        float2* dst;
        if (c4 < 8) {
            int c = c4 * 4;
            s.x += bq[c]; s.y += bq[c + 1]; s.z += bq[c + 2]; s.w += bq[c + 3];
            dst = &g_Qhl[(size_t)(row0 + row) * 32 + c];
        } else {
            int c = c4 * 4 - 32;
            s.x += bk[c]; s.y += bk[c + 1]; s.z += bk[c + 2]; s.w += bk[c + 3];
            dst = &g_Khl[(size_t)(row0 + row) * 32 + c];
        }
        float2 p0 = tf_split(s.x), q1 = tf_split(s.y),
               q2 = tf_split(s.z), q3 = tf_split(s.w);
        *(float4*)&dst[0] = make_float4(p0.x, p0.y, q1.x, q1.y);
        *(float4*)&dst[2] = make_float4(q2.x, q2.y, q3.x, q3.y);
    }
}

// ---------------------------------------------------------------------------
// Kernel 3: similarity (tf32x3 MMA, SPLIT accumulators hh/hl/lh) + top-4.
// grid = 512 (256 row-tiles x 2 key-halves), 256 thr, 16 tiles of 64 keys.
// ---------------------------------------------------------------------------
__global__ __launch_bounds__(256) void sim_mma()
{
    __shared__ float4 Kt[2][64][17];    // [key][j] paired-k
    __shared__ float  Mv[32][8];
    __shared__ int    Mi[32][8];

    const int tid = threadIdx.x, lane = tid & 31, warp = tid >> 5;
    const int g = lane >> 2, t = lane & 3;
    const int rbase = (warp >> 1) * 8;
    const int kh    = (warp & 1) * 32;
    const int row0  = (blockIdx.x >> 1) * 32;
    const int khalf = blockIdx.x & 1;
    const int bb    = row0 >> 11;

    // query B-fragments in registers (tile-invariant)
    float2 bq0[4], bq1[4];
    {
        const float2* qrow = &g_Qhl[(size_t)(row0 + rbase + g) * 32];
        #pragma unroll
        for (int k8 = 0; k8 < 4; k8++) {
            bq0[k8] = qrow[k8 * 8 + t];
            bq1[k8] = qrow[k8 * 8 + t + 4];
        }
    }

    const float2* Kb = &g_Khl[(size_t)bb * TT * 32];
    const int sk = tid >> 2, sk8 = tid & 3;
    float4 pr[4];
    auto ldg = [&](int tile) {
        const float4* src = (const float4*)
            &Kb[(size_t)(khalf * 1024 + tile * 64 + sk) * 32 + sk8 * 8];
        #pragma unroll
        for (int l = 0; l < 4; l++) pr[l] = src[l];
    };
    auto sts = [&](int bf) {
        Kt[bf][sk][sk8 * 4 + 0] = make_float4(pr[0].x, pr[0].y, pr[2].x, pr[2].y);
        Kt[bf][sk][sk8 * 4 + 1] = make_float4(pr[0].z, pr[0].w, pr[2].z, pr[2].w);
        Kt[bf][sk][sk8 * 4 + 2] = make_float4(pr[1].x, pr[1].y, pr[3].x, pr[3].y);
        Kt[bf][sk][sk8 * 4 + 3] = make_float4(pr[1].z, pr[1].w, pr[3].z, pr[3].w);
    };

    float tvA[4], tvB[4]; int tiA[4], tiB[4];
    #pragma unroll
    for (int p = 0; p < 4; p++) {
        tvA[p] = tvB[p] = -INFINITY; tiA[p] = tiB[p] = 0;
    }

    ldg(0); sts(0);
    __syncthreads();

    for (int tile = 0; tile < 16; tile++) {
        const int bf = tile & 1;
        if (tile < 15) ldg(tile + 1);

        // SPLIT accumulators: 6 independent HMMA chains per thread
        float hh[2][4], hl[2][4], lh[2][4];
        #pragma unroll
        for (int i = 0; i < 2; i++)
            #pragma unroll
            for (int j = 0; j < 4; j++) { hh[i][j] = hl[i][j] = lh[i][j] = 0.0f; }

        #pragma unroll
        for (int k8 = 0; k8 < 4; k8++) {
            const int j = k8 * 4 + t;
            const unsigned bh0 = __float_as_uint(bq0[k8].x);
            const unsigned bh1 = __float_as_uint(bq1[k8].x);
            const unsigned bl0 = __float_as_uint(bq0[k8].y);
            const unsigned bl1 = __float_as_uint(bq1[k8].y);
            #pragma unroll
            for (int mt = 0; mt < 2; mt++) {
                const int kl = kh + mt * 16;
                float4 av0 = Kt[bf][kl + g][j];      // (hi_k, lo_k, hi_k4, lo_k4)
                float4 av1 = Kt[bf][kl + g + 8][j];
                const unsigned ah0 = __float_as_uint(av0.x), ah1 = __float_as_uint(av1.x);
                const unsigned ah2 = __float_as_uint(av0.z), ah3 = __float_as_uint(av1.z);
                const unsigned al0 = __float_as_uint(av0.y), al1 = __float_as_uint(av1.y);
                const unsigned al2 = __float_as_uint(av0.w), al3 = __float_as_uint(av1.w);
                mma8(hh[mt], ah0, ah1, ah2, ah3, bh0, bh1);
                mma8(hl[mt], ah0, ah1, ah2, ah3, bl0, bl1);
                mma8(lh[mt], al0, al1, al2, al3, bh0, bh1);
            }
        }

        // combine terms
        float acc[2][4];
        #pragma unroll
        for (int mt = 0; mt < 2; mt++)
            #pragma unroll
            for (int j = 0; j < 4; j++)
                acc[mt][j] = (hl[mt][j] + lh[mt][j]) + hh[mt][j];

        const int kb0 = khalf * 1024 + tile * 64 + kh + g;
        {
            float v0 = acc[0][0], v1 = acc[0][2], v2 = acc[1][0], v3 = acc[1][2];
            float m = fmaxf(fmaxf(v0, v1), fmaxf(v2, v3));
            if (m > tvA[3]) {
                upd4(tvA, tiA, v0, kb0);
                upd4(tvA, tiA, v1, kb0 + 8);
                upd4(tvA, tiA, v2, kb0 + 16);
                upd4(tvA, tiA, v3, kb0 + 24);
            }
        }
        {
            float v0 = acc[0][1], v1 = acc[0][3], v2 = acc[1][1], v3 = acc[1][3];
            float m = fmaxf(fmaxf(v0, v1), fmaxf(v2, v3));
            if (m > tvB[3]) {
                upd4(tvB, tiB, v0, kb0);
                upd4(tvB, tiB, v1, kb0 + 8);
                upd4(tvB, tiB, v2, kb0 + 16);
                upd4(tvB, tiB, v3, kb0 + 24);
            }
        }

        if (tile < 15) {
            sts(bf ^ 1);
            __syncthreads();
        }
    }

    // merge across g-lanes (xor 4,8,16), snapshot then insert
    #pragma unroll
    for (int off = 4; off <= 16; off <<= 1) {
        float ov[4]; int oi[4];
        #pragma unroll
        for (int p = 0; p < 4; p++) {
            ov[p] = __shfl_xor_sync(0xFFFFFFFFu, tvA[p], off);
            oi[p] = __shfl_xor_sync(0xFFFFFFFFu, tiA[p], off);
        }
        #pragma unroll
        for (int p = 0; p < 4; p++) upd4(tvA, tiA, ov[p], oi[p]);
        #pragma unroll
        for (int p = 0; p < 4; p++) {
            ov[p] = __shfl_xor_sync(0xFFFFFFFFu, tvB[p], off);
            oi[p] = __shfl_xor_sync(0xFFFFFFFFu, tiB[p], off);
        }
        #pragma unroll
        for (int p = 0; p < 4; p++) upd4(tvB, tiB, ov[p], oi[p]);
    }

    // in-block merge of the two kh-warps (separate smem slots per kh)
    if (g == 0) {
        const int kcol = (warp & 1) * 4;
        #pragma unroll
        for (int p = 0; p < 4; p++) {
            Mv[rbase + 2 * t][kcol + p]     = tvA[p];
            Mi[rbase + 2 * t][kcol + p]     = tiA[p];
            Mv[rbase + 2 * t + 1][kcol + p] = tvB[p];
            Mi[rbase + 2 * t + 1][kcol + p] = tiB[p];
        }
    }
    __syncthreads();

    if (tid < 32) {
        float cv[8]; int ci[8];
        #pragma unroll
        for (int k = 0; k < 8; k++) { cv[k] = Mv[tid][k]; ci[k] = Mi[tid][k]; }
        float ov[4]; int oi[4];
        #pragma unroll
        for (int p = 0; p < KTOP; p++) {
            int best = 0;
            #pragma unroll
            for (int k = 1; k < 8; k++)
                if (cv[k] > cv[best]) best = k;
            ov[p] = cv[best]; oi[p] = ci[best];
            cv[best] = -INFINITY;
        }
        const size_t base = (size_t)(row0 + tid) * 8 + khalf * 4;
        *(float4*)&g_cv[base] = make_float4(ov[0], ov[1], ov[2], ov[3]);
        *(int4*)&g_ci[base]   = make_int4(oi[0], oi[1], oi[2], oi[3]);
    }
}

// ---------------------------------------------------------------------------
// Kernel 4 (R5-proven): merge 8 candidates + gather + mean. Warp per row.
// ---------------------------------------------------------------------------
__global__ __launch_bounds__(256) void gather_kernel(
    const float* __restrict__ x, float* __restrict__ out)
{
    const int tid  = threadIdx.x;
    const int wid  = tid >> 5;
    const int lane = tid & 31;
    const int row  = blockIdx.x * 8 + wid;
    const int b    = row >> 11;

    float cv[8]; int ci[8];
    {
        float4 a = *(const float4*)&g_cv[(size_t)row * 8];
        float4 c2 = *(const float4*)&g_cv[(size_t)row * 8 + 4];
        int4 ia = *(const int4*)&g_ci[(size_t)row * 8];
        int4 ib = *(const int4*)&g_ci[(size_t)row * 8 + 4];
        cv[0] = a.x; cv[1] = a.y; cv[2] = a.z; cv[3] = a.w;
        cv[4] = c2.x; cv[5] = c2.y; cv[6] = c2.z; cv[7] = c2.w;
        ci[0] = ia.x; ci[1] = ia.y; ci[2] = ia.z; ci[3] = ia.w;
        ci[4] = ib.x; ci[5] = ib.y; ci[6] = ib.z; ci[7] = ib.w;
    }
    int sel[4];
    #pragma unroll
    for (int p = 0; p < KTOP; p++) {
        int best = 0;
        #pragma unroll
        for (int k = 1; k < 8; k++)
            if (cv[k] > cv[best]) best = k;
        sel[p] = ci[best];
        cv[best] = -INFINITY;
    }

    const float4* xb4 = (const float4*)(x + (size_t)b * TT * DD);
    const float4* n0 = xb4 + (size_t)sel[0] * 256;
    const float4* n1 = xb4 + (size_t)sel[1] * 256;
    const float4* n2 = xb4 + (size_t)sel[2] * 256;
    const float4* n3 = xb4 + (size_t)sel[3] * 256;
    float4* o4 = (float4*)out + (size_t)row * 256;

    #pragma unroll
    for (int j = 0; j < 8; j++) {
        int c = lane + j * 32;
        float4 A = n0[c], B = n1[c], C = n2[c], D = n3[c];
        float4 o;
        o.x = (A.x + B.x + C.x + D.x) * 0.25f;
        o.y = (A.y + B.y + C.y + D.y) * 0.25f;
        o.z = (A.z + B.z + C.z + D.z) * 0.25f;
        o.w = (A.w + B.w + C.w + D.w) * 0.25f;
        o4[c] = o;
    }
}

// ---------------------------------------------------------------------------
extern "C" void kernel_launch(void* const* d_in, const int* in_sizes, int n_in,
                              void* d_out, int out_size)
{
    const float* x  = (const float*)d_in[0];
    const float* Wq = (const float*)d_in[1];
    const float* bq = (const float*)d_in[2];
    const float* Wk = (const float*)d_in[3];
    const float* bk = (const float*)d_in[4];
    float* out = (float*)d_out;

    proj_kernel<<<512, 256>>>(x, Wq, Wk);
    reduce_split<<<128, 256>>>(bq, bk);
    sim_mma<<<512, 256>>>();
    gather_kernel<<<1024, 256>>>(x, out);
}

// round 15
// speedup vs baseline: 1.1712x; 1.1712x over previous
#include <cuda_runtime.h>
#include <math.h>

#define TT 2048
#define DD 1024
#define KQ 32
#define NT 8192
#define KTOP 4

typedef unsigned long long ull;

// scratch
__device__ float g_P[4][NT * 64];           // proj partials (k-split 4)
__device__ float g_Qf[NT * KQ];             // reduced Q [row][k]
__device__ float g_Kf[NT * KQ];             // reduced K [row][k]
__device__ float g_cv[NT * 8];              // candidate values [row][half][4]
__device__ __align__(16) int g_ci[NT * 8];  // candidate indices

// ---- packed f32x2 helpers ---------------------------------------------------
__device__ __forceinline__ void unpack2(ull v, float& lo, float& hi) {
    asm("mov.b64 {%0, %1}, %2;" : "=f"(lo), "=f"(hi) : "l"(v));
}
__device__ __forceinline__ ull ffma2(ull a, ull b, ull c) {
    ull d;
    asm("fma.rn.f32x2 %0, %1, %2, %3;" : "=l"(d) : "l"(a), "l"(b), "l"(c));
    return d;
}

// sorted top-4 insert (v0>=v1>=v2>=v3)
__device__ __forceinline__ void upd4(float* v, int* ix, float s, int si) {
    if (s > v[3]) {
        if (s > v[1]) {
            v[3] = v[2]; ix[3] = ix[2]; v[2] = v[1]; ix[2] = ix[1];
            if (s > v[0]) { v[1] = v[0]; ix[1] = ix[0]; v[0] = s; ix[0] = si; }
            else          { v[1] = s; ix[1] = si; }
        } else {
            if (s > v[2]) { v[3] = v[2]; ix[3] = ix[2]; v[2] = s; ix[2] = si; }
            else          { v[3] = s; ix[3] = si; }
        }
    }
}

// ---------------------------------------------------------------------------
// Kernel 1 (R5-proven): projection partials. grid = 512, 256 thr.
// ---------------------------------------------------------------------------
__global__ __launch_bounds__(256) void proj_kernel(
    const float* __restrict__ x, const float* __restrict__ Wq,
    const float* __restrict__ Wk)
{
    __shared__ __align__(16) float Xd[32][132];  // [k][2*row] duplicated pairs
    __shared__ __align__(16) float Wt[32][68];   // [k][col]

    const int tid  = threadIdx.x;
    const int row0 = (blockIdx.x >> 2) * 64;
    const int kh   = blockIdx.x & 3;
    const int rg   = tid >> 4;
    const int tc   = tid & 15;
    const int r0   = rg * 4;

    ull acc[4][2];
    #pragma unroll
    for (int i = 0; i < 4; i++) { acc[i][0] = 0ULL; acc[i][1] = 0ULL; }

    for (int kt = 0; kt < 8; kt++) {
        const int kb = kh * 256 + kt * 32;
        #pragma unroll
        for (int l = 0; l < 2; l++) {
            int f = tid + l * 256;
            int row = f >> 3, kc = f & 7;
            float4 v = *(const float4*)&x[(size_t)(row0 + row) * DD + kb + kc * 4];
            *(float2*)&Xd[kc * 4 + 0][2 * row] = make_float2(v.x, v.x);
            *(float2*)&Xd[kc * 4 + 1][2 * row] = make_float2(v.y, v.y);
            *(float2*)&Xd[kc * 4 + 2][2 * row] = make_float2(v.z, v.z);
            *(float2*)&Xd[kc * 4 + 3][2 * row] = make_float2(v.w, v.w);
        }
        #pragma unroll
        for (int l = 0; l < 2; l++) {
            int f = tid + l * 256;
            int col = f >> 3, kc = f & 7;
            const float* Wr = (col < KQ) ? &Wq[col * DD] : &Wk[(col - KQ) * DD];
            float4 w = *(const float4*)&Wr[kb + kc * 4];
            Wt[kc * 4 + 0][col] = w.x;
            Wt[kc * 4 + 1][col] = w.y;
            Wt[kc * 4 + 2][col] = w.z;
            Wt[kc * 4 + 3][col] = w.w;
        }
        __syncthreads();

        #pragma unroll
        for (int k = 0; k < 32; k++) {
            ulonglong2 xa = *(const ulonglong2*)&Xd[k][2 * r0];
            ulonglong2 xb = *(const ulonglong2*)&Xd[k][2 * r0 + 4];
            ull w0 = *(const ull*)&Wt[k][2 * tc];
            ull w1 = *(const ull*)&Wt[k][2 * tc + 32];
            ull xr[4] = { xa.x, xa.y, xb.x, xb.y };
            #pragma unroll
            for (int i = 0; i < 4; i++) {
                acc[i][0] = ffma2(xr[i], w0, acc[i][0]);
                acc[i][1] = ffma2(xr[i], w1, acc[i][1]);
            }
        }
        __syncthreads();
    }

    #pragma unroll
    for (int i = 0; i < 4; i++) {
        size_t r = (size_t)(row0 + r0 + i) * 64;
        float lo, hi;
        unpack2(acc[i][0], lo, hi);
        *(float2*)&g_P[kh][r + 2 * tc] = make_float2(lo, hi);
        unpack2(acc[i][1], lo, hi);
        *(float2*)&g_P[kh][r + 2 * tc + 32] = make_float2(lo, hi);
    }
}

// ---------------------------------------------------------------------------
// Kernel 2: reduce partials + bias; emit Q and K, both [row][k] plain float.
// grid = 128, 256 thr.
// ---------------------------------------------------------------------------
__global__ __launch_bounds__(256) void reduce_kernel(
    const float* __restrict__ bq, const float* __restrict__ bk)
{
    const int tid  = threadIdx.x;
    const int row0 = blockIdx.x * 64;

    #pragma unroll
    for (int l = 0; l < 4; l++) {
        int f = tid + l * 256;
        int row = f >> 4, c4 = f & 15;
        size_t base = (size_t)(row0 + row) * 64 + c4 * 4;
        float4 a = *(const float4*)&g_P[0][base];
        float4 p1 = *(const float4*)&g_P[1][base];
        float4 p2 = *(const float4*)&g_P[2][base];
        float4 p3 = *(const float4*)&g_P[3][base];
        float4 s;
        s.x = ((a.x + p1.x) + p2.x) + p3.x;
        s.y = ((a.y + p1.y) + p2.y) + p3.y;
        s.z = ((a.z + p1.z) + p2.z) + p3.z;
        s.w = ((a.w + p1.w) + p2.w) + p3.w;
        if (c4 < 8) {
            int c = c4 * 4;
            s.x += bq[c]; s.y += bq[c + 1]; s.z += bq[c + 2]; s.w += bq[c + 3];
            *(float4*)&g_Qf[(size_t)(row0 + row) * KQ + c] = s;
        } else {
            int c = c4 * 4 - 32;
            s.x += bk[c]; s.y += bk[c + 1]; s.z += bk[c + 2]; s.w += bk[c + 3];
            *(float4*)&g_Kf[(size_t)(row0 + row) * KQ + c] = s;
        }
    }
}

// ---------------------------------------------------------------------------
// Kernel 3 (R3-structure FFMA2 sim, key-split x2): grid = 512, 128 thr.
// Block: 32 rows x 1024 keys (8 tiles of 128). Thread: 4 rows x 4 key-pairs
// (16 independent FFMA2 chains). 16-lane shuffle merge, candidate write.
// ---------------------------------------------------------------------------
__global__ __launch_bounds__(128) void sim_topk(
)
{
    __shared__ __align__(16) float Qd[32][68];    // [k][2*row] duplicated
    __shared__ __align__(16) float Kt[32][132];   // [k][key]

    const int tid   = threadIdx.x;
    const int row0  = (blockIdx.x >> 1) * 32;
    const int khalf = blockIdx.x & 1;
    const int b     = row0 >> 11;
    const int rg    = tid >> 4;     // 0..7 -> rows r0..r0+3
    const int cg    = tid & 15;     // key-pair group
    const int r0    = rg * 4;

    // stage Q (32 rows x 32 k) duplicated pairs
    #pragma unroll
    for (int l = 0; l < 2; l++) {
        int f = tid + l * 128;
        int row = f >> 3, kc = f & 7;
        float4 v = *(const float4*)&g_Qf[(size_t)(row0 + row) * KQ + kc * 4];
        *(float2*)&Qd[kc * 4 + 0][2 * row] = make_float2(v.x, v.x);
        *(float2*)&Qd[kc * 4 + 1][2 * row] = make_float2(v.y, v.y);
        *(float2*)&Qd[kc * 4 + 2][2 * row] = make_float2(v.z, v.z);
        *(float2*)&Qd[kc * 4 + 3][2 * row] = make_float2(v.w, v.w);
    }

    float tv[4][4]; int ti[4][4];
    #pragma unroll
    for (int i = 0; i < 4; i++)
        #pragma unroll
        for (int p = 0; p < 4; p++) { tv[i][p] = -INFINITY; ti[i][p] = 0; }

    const float* Kb = &g_Kf[((size_t)b * TT + khalf * 1024) * KQ];

    for (int t = 0; t < 8; t++) {
        const int kbase = t * 128;
        __syncthreads();   // Qd ready (t=0) / Kt consumed (t>0)
        // stage K tile (128 keys x 32 k) from final K [row][k]
        #pragma unroll
        for (int l = 0; l < 8; l++) {
            int f = tid + l * 128;
            int key = f >> 3, kc = f & 7;
            float4 v = *(const float4*)&Kb[(size_t)(kbase + key) * KQ + kc * 4];
            Kt[kc * 4 + 0][key] = v.x;
            Kt[kc * 4 + 1][key] = v.y;
            Kt[kc * 4 + 2][key] = v.z;
            Kt[kc * 4 + 3][key] = v.w;
        }
        __syncthreads();

        ull acc[4][4];
        #pragma unroll
        for (int i = 0; i < 4; i++)
            #pragma unroll
            for (int j = 0; j < 4; j++) acc[i][j] = 0ULL;

        #pragma unroll
        for (int k = 0; k < 32; k++) {
            ulonglong2 qa = *(const ulonglong2*)&Qd[k][2 * r0];
            ulonglong2 qb = *(const ulonglong2*)&Qd[k][2 * r0 + 4];
            ull k0 = *(const ull*)&Kt[k][2 * cg];
            ull k1 = *(const ull*)&Kt[k][2 * cg + 32];
            ull k2 = *(const ull*)&Kt[k][2 * cg + 64];
            ull k3 = *(const ull*)&Kt[k][2 * cg + 96];
            ull qr[4] = { qa.x, qa.y, qb.x, qb.y };
            #pragma unroll
            for (int i = 0; i < 4; i++) {
                acc[i][0] = ffma2(qr[i], k0, acc[i][0]);
                acc[i][1] = ffma2(qr[i], k1, acc[i][1]);
                acc[i][2] = ffma2(qr[i], k2, acc[i][2]);
                acc[i][3] = ffma2(qr[i], k3, acc[i][3]);
            }
        }

        // prefiltered top-4 update
        const int ib = khalf * 1024 + kbase + 2 * cg;
        #pragma unroll
        for (int i = 0; i < 4; i++) {
            float v[8];
            unpack2(acc[i][0], v[0], v[1]);
            unpack2(acc[i][1], v[2], v[3]);
            unpack2(acc[i][2], v[4], v[5]);
            unpack2(acc[i][3], v[6], v[7]);
            float m = fmaxf(fmaxf(fmaxf(v[0], v[1]), fmaxf(v[2], v[3])),
                            fmaxf(fmaxf(v[4], v[5]), fmaxf(v[6], v[7])));
            if (m > tv[i][3]) {
                upd4(tv[i], ti[i], v[0], ib);
                upd4(tv[i], ti[i], v[1], ib + 1);
                upd4(tv[i], ti[i], v[2], ib + 32);
                upd4(tv[i], ti[i], v[3], ib + 33);
                upd4(tv[i], ti[i], v[4], ib + 64);
                upd4(tv[i], ti[i], v[5], ib + 65);
                upd4(tv[i], ti[i], v[6], ib + 96);
                upd4(tv[i], ti[i], v[7], ib + 97);
            }
        }
    }

    // 16-lane shuffle merge (cg lanes of each rg are contiguous within a warp;
    // xor offsets 1,2,4,8 stay inside the 16-lane group). Snapshot then insert.
    #pragma unroll
    for (int off = 1; off <= 8; off <<= 1) {
        #pragma unroll
        for (int i = 0; i < 4; i++) {
            float ov[4]; int oi[4];
            #pragma unroll
            for (int p = 0; p < 4; p++) {
                ov[p] = __shfl_xor_sync(0xFFFFFFFFu, tv[i][p], off);
                oi[p] = __shfl_xor_sync(0xFFFFFFFFu, ti[i][p], off);
            }
            #pragma unroll
            for (int p = 0; p < 4; p++)
                upd4(tv[i], ti[i], ov[p], oi[p]);
        }
    }

    if (cg == 0) {
        #pragma unroll
        for (int i = 0; i < 4; i++) {
            size_t base = (size_t)(row0 + r0 + i) * 8 + khalf * 4;
            *(float4*)&g_cv[base] = make_float4(tv[i][0], tv[i][1], tv[i][2], tv[i][3]);
            *(int4*)&g_ci[base]   = make_int4(ti[i][0], ti[i][1], ti[i][2], ti[i][3]);
        }
    }
}

// ---------------------------------------------------------------------------
// Kernel 4 (R5-proven): merge 8 candidates + gather + mean. Warp per row.
// ---------------------------------------------------------------------------
__global__ __launch_bounds__(256) void gather_kernel(
    const float* __restrict__ x, float* __restrict__ out)
{
    const int tid  = threadIdx.x;
    const int wid  = tid >> 5;
    const int lane = tid & 31;
    const int row  = blockIdx.x * 8 + wid;
    const int b    = row >> 11;

    float cv[8]; int ci[8];
    {
        float4 a = *(const float4*)&g_cv[(size_t)row * 8];
        float4 c2 = *(const float4*)&g_cv[(size_t)row * 8 + 4];
        int4 ia = *(const int4*)&g_ci[(size_t)row * 8];
        int4 ib = *(const int4*)&g_ci[(size_t)row * 8 + 4];
        cv[0] = a.x; cv[1] = a.y; cv[2] = a.z; cv[3] = a.w;
        cv[4] = c2.x; cv[5] = c2.y; cv[6] = c2.z; cv[7] = c2.w;
        ci[0] = ia.x; ci[1] = ia.y; ci[2] = ia.z; ci[3] = ia.w;
        ci[4] = ib.x; ci[5] = ib.y; ci[6] = ib.z; ci[7] = ib.w;
    }
    int sel[4];
    #pragma unroll
    for (int p = 0; p < KTOP; p++) {
        int best = 0;
        #pragma unroll
        for (int k = 1; k < 8; k++)
            if (cv[k] > cv[best]) best = k;
        sel[p] = ci[best];
        cv[best] = -INFINITY;
    }

    const float4* xb4 = (const float4*)(x + (size_t)b * TT * DD);
    const float4* n0 = xb4 + (size_t)sel[0] * 256;
    const float4* n1 = xb4 + (size_t)sel[1] * 256;
    const float4* n2 = xb4 + (size_t)sel[2] * 256;
    const float4* n3 = xb4 + (size_t)sel[3] * 256;
    float4* o4 = (float4*)out + (size_t)row * 256;

    #pragma unroll
    for (int j = 0; j < 8; j++) {
        int c = lane + j * 32;
        float4 A = n0[c], B = n1[c], C = n2[c], D = n3[c];
        float4 o;
        o.x = (A.x + B.x + C.x + D.x) * 0.25f;
        o.y = (A.y + B.y + C.y + D.y) * 0.25f;
        o.z = (A.z + B.z + C.z + D.z) * 0.25f;
        o.w = (A.w + B.w + C.w + D.w) * 0.25f;
        o4[c] = o;
    }
}

// ---------------------------------------------------------------------------
extern "C" void kernel_launch(void* const* d_in, const int* in_sizes, int n_in,
                              void* d_out, int out_size)
{
    const float* x  = (const float*)d_in[0];
    const float* Wq = (const float*)d_in[1];
    const float* bq = (const float*)d_in[2];
    const float* Wk = (const float*)d_in[3];
    const float* bk = (const float*)d_in[4];
    float* out = (float*)d_out;

    proj_kernel<<<512, 256>>>(x, Wq, Wk);
    reduce_kernel<<<128, 256>>>(bq, bk);
    sim_topk<<<512, 128>>>();
    gather_kernel<<<1024, 256>>>(x, out);
}

// round 16
// speedup vs baseline: 1.1892x; 1.0154x over previous
#include <cuda_runtime.h>
#include <math.h>

#define TT 2048
#define DD 1024
#define KQ 32
#define NT 8192
#define KTOP 4

typedef unsigned long long ull;

// scratch
__device__ float g_P[4][NT * 64];           // proj partials (k-split 4)
__device__ float g_Qf[NT * KQ];             // reduced Q [row][k]
__device__ float g_Kf[NT * KQ];             // reduced K [row][k]
__device__ float g_cv[NT * 8];              // candidate values [row][half][4]
__device__ __align__(16) int g_ci[NT * 8];  // candidate indices

// ---- packed f32x2 helpers ---------------------------------------------------
__device__ __forceinline__ void unpack2(ull v, float& lo, float& hi) {
    asm("mov.b64 {%0, %1}, %2;" : "=f"(lo), "=f"(hi) : "l"(v));
}
__device__ __forceinline__ ull ffma2(ull a, ull b, ull c) {
    ull d;
    asm("fma.rn.f32x2 %0, %1, %2, %3;" : "=l"(d) : "l"(a), "l"(b), "l"(c));
    return d;
}

// sorted top-4 insert (v0>=v1>=v2>=v3)
__device__ __forceinline__ void upd4(float* v, int* ix, float s, int si) {
    if (s > v[3]) {
        if (s > v[1]) {
            v[3] = v[2]; ix[3] = ix[2]; v[2] = v[1]; ix[2] = ix[1];
            if (s > v[0]) { v[1] = v[0]; ix[1] = ix[0]; v[0] = s; ix[0] = si; }
            else          { v[1] = s; ix[1] = si; }
        } else {
            if (s > v[2]) { v[3] = v[2]; ix[3] = ix[2]; v[2] = s; ix[2] = si; }
            else          { v[3] = s; ix[3] = si; }
        }
    }
}

// ---------------------------------------------------------------------------
// Kernel 1: projection partials, register-prefetched. grid = 512, 256 thr.
// Block: 64 rows x 64 cols x 256 k. Thread: 4 rows x 4 cols (LDS.128 W).
// ---------------------------------------------------------------------------
__global__ __launch_bounds__(256) void proj_kernel(
    const float* __restrict__ x, const float* __restrict__ Wq,
    const float* __restrict__ Wk)
{
    __shared__ __align__(16) float Xd[32][132];  // [k][2*row] duplicated pairs
    __shared__ __align__(16) float Wt[32][68];   // [k][col]

    const int tid  = threadIdx.x;
    const int row0 = (blockIdx.x >> 2) * 64;
    const int kh   = blockIdx.x & 3;
    const int rg   = tid >> 4;      // 0..15
    const int tc   = tid & 15;      // cols 4tc..4tc+3
    const int r0   = rg * 4;

    // loader coords: row/col = tid>>3 and +32; kc = tid&7
    const int lrow = tid >> 3;
    const int lk4  = (tid & 7) * 4;
    const float* xrowA = &x[(size_t)(row0 + lrow) * DD];
    const float* xrowB = &x[(size_t)(row0 + lrow + 32) * DD];
    const float* WrA = (lrow < KQ) ? &Wq[lrow * DD] : &Wk[(lrow - KQ) * DD];
    const float* WrB = &Wk[(lrow + 32 - KQ) * DD];

    float4 px0, px1, pw0, pw1;
    auto ldg = [&](int kt) {
        const int kb = kh * 256 + kt * 32 + lk4;
        px0 = *(const float4*)&xrowA[kb];
        px1 = *(const float4*)&xrowB[kb];
        pw0 = *(const float4*)&WrA[kb];
        pw1 = *(const float4*)&WrB[kb];
    };
    auto sts = [&]() {
        const float* xv0 = (const float*)&px0;
        const float* xv1 = (const float*)&px1;
        const float* wv0 = (const float*)&pw0;
        const float* wv1 = (const float*)&pw1;
        #pragma unroll
        for (int i = 0; i < 4; i++) {
            *(float2*)&Xd[lk4 + i][2 * lrow]        = make_float2(xv0[i], xv0[i]);
            *(float2*)&Xd[lk4 + i][2 * (lrow + 32)] = make_float2(xv1[i], xv1[i]);
            Wt[lk4 + i][lrow]      = wv0[i];
            Wt[lk4 + i][lrow + 32] = wv1[i];
        }
    };

    ull acc[4][2];
    #pragma unroll
    for (int i = 0; i < 4; i++) { acc[i][0] = 0ULL; acc[i][1] = 0ULL; }

    ldg(0); sts();
    __syncthreads();

    for (int kt = 0; kt < 8; kt++) {
        if (kt < 7) ldg(kt + 1);      // LDG in flight during compute
        #pragma unroll
        for (int k = 0; k < 32; k++) {
            ulonglong2 xa = *(const ulonglong2*)&Xd[k][2 * r0];
            ulonglong2 xb = *(const ulonglong2*)&Xd[k][2 * r0 + 4];
            ulonglong2 wp = *(const ulonglong2*)&Wt[k][4 * tc];  // cols 4tc..4tc+3
            ull xr[4] = { xa.x, xa.y, xb.x, xb.y };
            #pragma unroll
            for (int i = 0; i < 4; i++) {
                acc[i][0] = ffma2(xr[i], wp.x, acc[i][0]);
                acc[i][1] = ffma2(xr[i], wp.y, acc[i][1]);
            }
        }
        __syncthreads();
        if (kt < 7) {
            sts();
            __syncthreads();
        }
    }

    #pragma unroll
    for (int i = 0; i < 4; i++) {
        size_t r = (size_t)(row0 + r0 + i) * 64;
        float l0, h0, l1, h1;
        unpack2(acc[i][0], l0, h0);
        unpack2(acc[i][1], l1, h1);
        *(float4*)&g_P[kh][r + 4 * tc] = make_float4(l0, h0, l1, h1);
    }
}

// ---------------------------------------------------------------------------
// Kernel 2: reduce partials + bias; emit Q and K, both [row][k] plain float.
// ---------------------------------------------------------------------------
__global__ __launch_bounds__(256) void reduce_kernel(
    const float* __restrict__ bq, const float* __restrict__ bk)
{
    const int tid  = threadIdx.x;
    const int row0 = blockIdx.x * 64;

    #pragma unroll
    for (int l = 0; l < 4; l++) {
        int f = tid + l * 256;
        int row = f >> 4, c4 = f & 15;
        size_t base = (size_t)(row0 + row) * 64 + c4 * 4;
        float4 a = *(const float4*)&g_P[0][base];
        float4 p1 = *(const float4*)&g_P[1][base];
        float4 p2 = *(const float4*)&g_P[2][base];
        float4 p3 = *(const float4*)&g_P[3][base];
        float4 s;
        s.x = ((a.x + p1.x) + p2.x) + p3.x;
        s.y = ((a.y + p1.y) + p2.y) + p3.y;
        s.z = ((a.z + p1.z) + p2.z) + p3.z;
        s.w = ((a.w + p1.w) + p2.w) + p3.w;
        if (c4 < 8) {
            int c = c4 * 4;
            s.x += bq[c]; s.y += bq[c + 1]; s.z += bq[c + 2]; s.w += bq[c + 3];
            *(float4*)&g_Qf[(size_t)(row0 + row) * KQ + c] = s;
        } else {
            int c = c4 * 4 - 32;
            s.x += bk[c]; s.y += bk[c + 1]; s.z += bk[c + 2]; s.w += bk[c + 3];
            *(float4*)&g_Kf[(size_t)(row0 + row) * KQ + c] = s;
        }
    }
}

// ---------------------------------------------------------------------------
// Kernel 3: FFMA2 sim, 64 rows/block, register-prefetched. grid = 256, 256 thr.
// Block: 64 rows x 1024 keys (8 tiles of 128). Thread: 4 rows x 8 keys
// (16 independent FFMA2 chains), K via LDS.128. 16-lane shuffle merge.
// ---------------------------------------------------------------------------
__global__ __launch_bounds__(256) void sim_topk()
{
    __shared__ __align__(16) float Qd[32][132];   // [k][2*row] duplicated, 64 rows
    __shared__ __align__(16) float Kt[32][132];   // [k][key], 128 keys

    const int tid   = threadIdx.x;
    const int row0  = (blockIdx.x >> 1) * 64;
    const int khalf = blockIdx.x & 1;
    const int b     = row0 >> 11;
    const int rg    = tid >> 4;     // 0..15 -> rows r0..r0+3
    const int cg    = tid & 15;     // keys 4cg..4cg+3, 4cg+64..4cg+67
    const int r0    = rg * 4;

    // stage Q (64 rows x 32 k) duplicated pairs
    #pragma unroll
    for (int l = 0; l < 2; l++) {
        int f = tid + l * 256;
        int row = f >> 3, kc = f & 7;
        float4 v = *(const float4*)&g_Qf[(size_t)(row0 + row) * KQ + kc * 4];
        *(float2*)&Qd[kc * 4 + 0][2 * row] = make_float2(v.x, v.x);
        *(float2*)&Qd[kc * 4 + 1][2 * row] = make_float2(v.y, v.y);
        *(float2*)&Qd[kc * 4 + 2][2 * row] = make_float2(v.z, v.z);
        *(float2*)&Qd[kc * 4 + 3][2 * row] = make_float2(v.w, v.w);
    }

    const float* Kb = &g_Kf[((size_t)b * TT + khalf * 1024) * KQ];
    const int skey = tid >> 3;          // key (l adds 32)
    const int skc  = (tid & 7) * 4;     // k offset
    float4 pr[4];
    auto ldg = [&](int t) {
        const int kbase = t * 128;
        #pragma unroll
        for (int l = 0; l < 4; l++)
            pr[l] = *(const float4*)&Kb[(size_t)(kbase + skey + l * 32) * KQ + skc];
    };
    auto sts = [&]() {
        #pragma unroll
        for (int l = 0; l < 4; l++) {
            const int key = skey + l * 32;
            Kt[skc + 0][key] = pr[l].x;
            Kt[skc + 1][key] = pr[l].y;
            Kt[skc + 2][key] = pr[l].z;
            Kt[skc + 3][key] = pr[l].w;
        }
    };

    float tv[4][4]; int ti[4][4];
    #pragma unroll
    for (int i = 0; i < 4; i++)
        #pragma unroll
        for (int p = 0; p < 4; p++) { tv[i][p] = -INFINITY; ti[i][p] = 0; }

    ldg(0); sts();
    __syncthreads();

    for (int t = 0; t < 8; t++) {
        if (t < 7) ldg(t + 1);

        ull acc[4][4];
        #pragma unroll
        for (int i = 0; i < 4; i++)
            #pragma unroll
            for (int j = 0; j < 4; j++) acc[i][j] = 0ULL;

        #pragma unroll
        for (int k = 0; k < 32; k++) {
            ulonglong2 qa = *(const ulonglong2*)&Qd[k][2 * r0];
            ulonglong2 qb = *(const ulonglong2*)&Qd[k][2 * r0 + 4];
            ulonglong2 k01 = *(const ulonglong2*)&Kt[k][4 * cg];        // keys 4cg..4cg+3
            ulonglong2 k23 = *(const ulonglong2*)&Kt[k][4 * cg + 64];   // +64
            ull qr[4] = { qa.x, qa.y, qb.x, qb.y };
            #pragma unroll
            for (int i = 0; i < 4; i++) {
                acc[i][0] = ffma2(qr[i], k01.x, acc[i][0]);
                acc[i][1] = ffma2(qr[i], k01.y, acc[i][1]);
                acc[i][2] = ffma2(qr[i], k23.x, acc[i][2]);
                acc[i][3] = ffma2(qr[i], k23.y, acc[i][3]);
            }
        }

        // prefiltered top-4 update
        const int ib = khalf * 1024 + t * 128 + 4 * cg;
        #pragma unroll
        for (int i = 0; i < 4; i++) {
            float v[8];
            unpack2(acc[i][0], v[0], v[1]);
            unpack2(acc[i][1], v[2], v[3]);
            unpack2(acc[i][2], v[4], v[5]);
            unpack2(acc[i][3], v[6], v[7]);
            float m = fmaxf(fmaxf(fmaxf(v[0], v[1]), fmaxf(v[2], v[3])),
                            fmaxf(fmaxf(v[4], v[5]), fmaxf(v[6], v[7])));
            if (m > tv[i][3]) {
                upd4(tv[i], ti[i], v[0], ib);
                upd4(tv[i], ti[i], v[1], ib + 1);
                upd4(tv[i], ti[i], v[2], ib + 2);
                upd4(tv[i], ti[i], v[3], ib + 3);
                upd4(tv[i], ti[i], v[4], ib + 64);
                upd4(tv[i], ti[i], v[5], ib + 65);
                upd4(tv[i], ti[i], v[6], ib + 66);
                upd4(tv[i], ti[i], v[7], ib + 67);
            }
        }

        __syncthreads();      // Kt fully consumed
        if (t < 7) {
            sts();
            __syncthreads();
        }
    }

    // 16-lane shuffle merge (snapshot then insert; xor 1,2,4,8 within cg group)
    #pragma unroll
    for (int off = 1; off <= 8; off <<= 1) {
        #pragma unroll
        for (int i = 0; i < 4; i++) {
            float ov[4]; int oi[4];
            #pragma unroll
            for (int p = 0; p < 4; p++) {
                ov[p] = __shfl_xor_sync(0xFFFFFFFFu, tv[i][p], off);
                oi[p] = __shfl_xor_sync(0xFFFFFFFFu, ti[i][p], off);
            }
            #pragma unroll
            for (int p = 0; p < 4; p++)
                upd4(tv[i], ti[i], ov[p], oi[p]);
        }
    }

    if (cg == 0) {
        #pragma unroll
        for (int i = 0; i < 4; i++) {
            size_t base = (size_t)(row0 + r0 + i) * 8 + khalf * 4;
            *(float4*)&g_cv[base] = make_float4(tv[i][0], tv[i][1], tv[i][2], tv[i][3]);
            *(int4*)&g_ci[base]   = make_int4(ti[i][0], ti[i][1], ti[i][2], ti[i][3]);
        }
    }
}

// ---------------------------------------------------------------------------
// Kernel 4 (R5-proven): merge 8 candidates + gather + mean. Warp per row.
// ---------------------------------------------------------------------------
__global__ __launch_bounds__(256) void gather_kernel(
    const float* __restrict__ x, float* __restrict__ out)
{
    const int tid  = threadIdx.x;
    const int wid  = tid >> 5;
    const int lane = tid & 31;
    const int row  = blockIdx.x * 8 + wid;
    const int b    = row >> 11;

    float cv[8]; int ci[8];
    {
        float4 a = *(const float4*)&g_cv[(size_t)row * 8];
        float4 c2 = *(const float4*)&g_cv[(size_t)row * 8 + 4];
        int4 ia = *(const int4*)&g_ci[(size_t)row * 8];
        int4 ib = *(const int4*)&g_ci[(size_t)row * 8 + 4];
        cv[0] = a.x; cv[1] = a.y; cv[2] = a.z; cv[3] = a.w;
        cv[4] = c2.x; cv[5] = c2.y; cv[6] = c2.z; cv[7] = c2.w;
        ci[0] = ia.x; ci[1] = ia.y; ci[2] = ia.z; ci[3] = ia.w;
        ci[4] = ib.x; ci[5] = ib.y; ci[6] = ib.z; ci[7] = ib.w;
    }
    int sel[4];
    #pragma unroll
    for (int p = 0; p < KTOP; p++) {
        int best = 0;
        #pragma unroll
        for (int k = 1; k < 8; k++)
            if (cv[k] > cv[best]) best = k;
        sel[p] = ci[best];
        cv[best] = -INFINITY;
    }

    const float4* xb4 = (const float4*)(x + (size_t)b * TT * DD);
    const float4* n0 = xb4 + (size_t)sel[0] * 256;
    const float4* n1 = xb4 + (size_t)sel[1] * 256;
    const float4* n2 = xb4 + (size_t)sel[2] * 256;
    const float4* n3 = xb4 + (size_t)sel[3] * 256;
    float4* o4 = (float4*)out + (size_t)row * 256;

    #pragma unroll
    for (int j = 0; j < 8; j++) {
        int c = lane + j * 32;
        float4 A = n0[c], B = n1[c], C = n2[c], D = n3[c];
        float4 o;
        o.x = (A.x + B.x + C.x + D.x) * 0.25f;
        o.y = (A.y + B.y + C.y + D.y) * 0.25f;
        o.z = (A.z + B.z + C.z + D.z) * 0.25f;
        o.w = (A.w + B.w + C.w + D.w) * 0.25f;
        o4[c] = o;
    }
}

// ---------------------------------------------------------------------------
extern "C" void kernel_launch(void* const* d_in, const int* in_sizes, int n_in,
                              void* d_out, int out_size)
{
    const float* x  = (const float*)d_in[0];
    const float* Wq = (const float*)d_in[1];
    const float* bq = (const float*)d_in[2];
    const float* Wk = (const float*)d_in[3];
    const float* bk = (const float*)d_in[4];
    float* out = (float*)d_out;

    proj_kernel<<<512, 256>>>(x, Wq, Wk);
    reduce_kernel<<<128, 256>>>(bq, bk);
    sim_topk<<<256, 256>>>();
    gather_kernel<<<1024, 256>>>(x, out);
}